// round 3
// baseline (speedup 1.0000x reference)
#include <cuda_runtime.h>
#include <math.h>

// Problem constants
constexpr int H_ = 1024;
constexpr int G_ = 4096;   // 4*H
constexpr int B_ = 32;
constexpr int T_ = 64;
constexpr int S_ = 64;
constexpr int L_ = 2;
constexpr int KT = 256;        // K tile
constexpr int XST = KT + 4;    // padded smem stride (words): 260 -> conflict-free LDS.128

// Scratch (device globals: sanctioned alternative to cudaMalloc)
__device__ float g_pre0[(size_t)T_ * G_ * B_];   // [t][j][b], j-major: 33.5 MB
__device__ float g_hbuf[2][L_][B_][H_];          // ping-pong h state
__device__ float g_c[L_][B_][H_];                // c state
__device__ float g_gamma[B_][H_];
__device__ float g_ctx[B_][H_];

__device__ __forceinline__ float sigf(float x) { return 1.f / (1.f + expf(-x)); }

// Warp computes NR output rows for all 32 batches (lane = b).
// W0 = pointer to (row0, col0) of this warp's rows; rows are rstride floats apart,
// columns contiguous. x = [B][H] activations. xs = smem tile (B*XST floats).
// blockDim must be 256.
template <int NR>
__device__ __forceinline__ void accum(float* acc, const float* __restrict__ W0,
                                      size_t rstride, const float* __restrict__ x,
                                      float* xs) {
    const int tid = threadIdx.x;
    const int lane = tid & 31;
    for (int k0 = 0; k0 < H_; k0 += KT) {
        __syncthreads();
        for (int i = tid; i < B_ * KT; i += 256) {
            int b = i >> 8;           // KT == 256
            int k = i & (KT - 1);
            xs[b * XST + k] = x[b * H_ + k0 + k];
        }
        __syncthreads();
        const float* xp = xs + lane * XST;
        const float* wp = W0 + k0;
#pragma unroll 4
        for (int k = 0; k < KT; k += 4) {
            float4 xv = *(const float4*)(xp + k);
#pragma unroll
            for (int r = 0; r < NR; r++) {
                float4 wv = *(const float4*)(wp + (size_t)r * rstride + k);
                acc[r] = fmaf(xv.x, wv.x, acc[r]);
                acc[r] = fmaf(xv.y, wv.y, acc[r]);
                acc[r] = fmaf(xv.z, wv.z, acc[r]);
                acc[r] = fmaf(xv.w, wv.w, acc[r]);
            }
        }
    }
}

// ---------------------------------------------------------------------------
// Precompute layer-0 input gates for ALL timesteps:
//   pre0[t][j][b] = b_ih0[j] + b_hh0[j] + dot(emb[tok[t][b]], W_ih0[j])
// grid (G/64, T), block 256: 8 warps x 8 rows
// ---------------------------------------------------------------------------
__global__ void __launch_bounds__(256) k_pre0(const int* __restrict__ tokens,
                                              const float* __restrict__ emb,
                                              const float* __restrict__ Wih0,
                                              const float* __restrict__ bih0,
                                              const float* __restrict__ bhh0) {
    __shared__ float xs[B_ * XST];
    __shared__ int tok_sh[B_];
    const int tid = threadIdx.x, wid = tid >> 5, lane = tid & 31;
    const int t = blockIdx.y;
    const int j0 = blockIdx.x * 64 + wid * 8;
    if (tid < B_) tok_sh[tid] = tokens[t * B_ + tid];

    float acc[8];
#pragma unroll
    for (int r = 0; r < 8; r++) acc[r] = bih0[j0 + r] + bhh0[j0 + r];

    for (int k0 = 0; k0 < H_; k0 += KT) {
        __syncthreads();
        for (int i = tid; i < B_ * KT; i += 256) {
            int b = i >> 8;
            int k = i & (KT - 1);
            xs[b * XST + k] = emb[(size_t)tok_sh[b] * H_ + k0 + k];
        }
        __syncthreads();
        const float* xp = xs + lane * XST;
        const float* wp = Wih0 + (size_t)j0 * H_ + k0;
#pragma unroll 2
        for (int k = 0; k < KT; k += 4) {
            float4 xv = *(const float4*)(xp + k);
#pragma unroll
            for (int r = 0; r < 8; r++) {
                float4 wv = *(const float4*)(wp + (size_t)r * H_ + k);
                acc[r] = fmaf(xv.x, wv.x, acc[r]);
                acc[r] = fmaf(xv.y, wv.y, acc[r]);
                acc[r] = fmaf(xv.z, wv.z, acc[r]);
                acc[r] = fmaf(xv.w, wv.w, acc[r]);
            }
        }
    }
    float* pre = g_pre0 + ((size_t)t * G_ + j0) * B_;
#pragma unroll
    for (int r = 0; r < 8; r++) pre[r * B_ + lane] = acc[r];   // [t][j0+r][b]
}

// ---------------------------------------------------------------------------
// Layer-0 LSTM cell: gates = pre0[t] + h0_prev @ Whh0^T, fused nonlinearity.
// grid 128, block 256: warp handles 1 jj (4 gate rows jj, jj+H, jj+2H, jj+3H).
// ---------------------------------------------------------------------------
__global__ void __launch_bounds__(256) k_cell0(const float* __restrict__ Whh0,
                                               int t, int cur) {
    __shared__ float xs[B_ * XST];
    const int tid = threadIdx.x, wid = tid >> 5, lane = tid & 31;
    const int jj = blockIdx.x * 8 + wid;

    float acc[4];
    const float* pre = g_pre0 + ((size_t)t * G_ + jj) * B_;
#pragma unroll
    for (int g = 0; g < 4; g++) acc[g] = pre[(size_t)g * H_ * B_ + lane];

    accum<4>(acc, Whh0 + (size_t)jj * H_, (size_t)H_ * H_,
             &g_hbuf[1 - cur][0][0][0], xs);

    float c1 = sigf(acc[1]) * g_c[0][lane][jj] + sigf(acc[0]) * tanhf(acc[2]);
    g_c[0][lane][jj] = c1;
    g_hbuf[cur][0][lane][jj] = sigf(acc[3]) * tanhf(c1);
}

// ---------------------------------------------------------------------------
// Layer-1 LSTM cell: gates = h0_cur @ Wih1^T + h1_prev @ Whh1^T + biases.
// ---------------------------------------------------------------------------
__global__ void __launch_bounds__(256) k_cell1(const float* __restrict__ Wih1,
                                               const float* __restrict__ Whh1,
                                               const float* __restrict__ bih1,
                                               const float* __restrict__ bhh1,
                                               int cur) {
    __shared__ float xs[B_ * XST];
    const int tid = threadIdx.x, wid = tid >> 5, lane = tid & 31;
    const int jj = blockIdx.x * 8 + wid;

    float acc[4];
#pragma unroll
    for (int g = 0; g < 4; g++) acc[g] = bih1[g * H_ + jj] + bhh1[g * H_ + jj];

    accum<4>(acc, Wih1 + (size_t)jj * H_, (size_t)H_ * H_,
             &g_hbuf[cur][0][0][0], xs);
    accum<4>(acc, Whh1 + (size_t)jj * H_, (size_t)H_ * H_,
             &g_hbuf[1 - cur][1][0][0], xs);

    float c1 = sigf(acc[1]) * g_c[1][lane][jj] + sigf(acc[0]) * tanhf(acc[2]);
    g_c[1][lane][jj] = c1;
    g_hbuf[cur][1][lane][jj] = sigf(acc[3]) * tanhf(c1);
}

// ---------------------------------------------------------------------------
// gamma = h1 @ W_in^T + b_in.  grid 128, 8 warps x 1 row.
// ---------------------------------------------------------------------------
__global__ void __launch_bounds__(256) k_gamma(const float* __restrict__ W_in,
                                               const float* __restrict__ b_in,
                                               int cur) {
    __shared__ float xs[B_ * XST];
    const int tid = threadIdx.x, wid = tid >> 5, lane = tid & 31;
    const int j = blockIdx.x * 8 + wid;
    float acc[1] = {b_in[j]};
    accum<1>(acc, W_in + (size_t)j * H_, 0, &g_hbuf[cur][1][0][0], xs);
    g_gamma[lane][j] = acc[0];
}

// ---------------------------------------------------------------------------
// Attention per batch element: scores, softmax, context. grid B, block 256.
// ---------------------------------------------------------------------------
__global__ void __launch_bounds__(256) k_attn(const float* __restrict__ contexts) {
    __shared__ float gs[H_];
    __shared__ float w_sh[S_];
    const int tid = threadIdx.x, wid = tid >> 5, lane = tid & 31;
    const int b = blockIdx.x;

    for (int i = tid; i < H_; i += 256) gs[i] = g_gamma[b][i];
    __syncthreads();

    // scores: 8 warps x 8 s each, lanes over k
#pragma unroll
    for (int si = 0; si < S_ / 8; si++) {
        int s = wid * (S_ / 8) + si;
        const float* cp = contexts + ((size_t)b * S_ + s) * H_;
        float a = 0.f;
        for (int k = lane; k < H_; k += 32) a = fmaf(cp[k], gs[k], a);
#pragma unroll
        for (int o = 16; o; o >>= 1) a += __shfl_xor_sync(0xffffffffu, a, o);
        if (lane == 0) w_sh[s] = a;
    }
    __syncthreads();

    // softmax over S=64 (warp 0, 2 values/lane)
    if (wid == 0) {
        float v0 = w_sh[lane], v1 = w_sh[lane + 32];
        float m = fmaxf(v0, v1);
#pragma unroll
        for (int o = 16; o; o >>= 1) m = fmaxf(m, __shfl_xor_sync(0xffffffffu, m, o));
        float e0 = expf(v0 - m), e1 = expf(v1 - m);
        float ssum = e0 + e1;
#pragma unroll
        for (int o = 16; o; o >>= 1) ssum += __shfl_xor_sync(0xffffffffu, ssum, o);
        float inv = 1.f / ssum;
        w_sh[lane] = e0 * inv;
        w_sh[lane + 32] = e1 * inv;
    }
    __syncthreads();

    // ctx[k] = sum_s w[s] * contexts[b][s][k]
#pragma unroll
    for (int i = 0; i < H_ / 256; i++) {
        int k = tid + i * 256;
        const float* cp = contexts + (size_t)b * S_ * H_ + k;
        float a = 0.f;
#pragma unroll 8
        for (int s = 0; s < S_; s++) a = fmaf(w_sh[s], cp[(size_t)s * H_], a);
        g_ctx[b][k] = a;
    }
}

// ---------------------------------------------------------------------------
// out[t][b][j] = tanh(b_out[j] + W_out[j,:H].ctx + W_out[j,H:].h1)
// ---------------------------------------------------------------------------
__global__ void __launch_bounds__(256) k_out(const float* __restrict__ W_out,
                                             const float* __restrict__ b_out,
                                             float* __restrict__ out, int t, int cur) {
    __shared__ float xs[B_ * XST];
    const int tid = threadIdx.x, wid = tid >> 5, lane = tid & 31;
    const int j = blockIdx.x * 8 + wid;
    float acc[1] = {b_out[j]};
    accum<1>(acc, W_out + (size_t)j * 2 * H_, 0, &g_ctx[0][0], xs);
    accum<1>(acc, W_out + (size_t)j * 2 * H_ + H_, 0, &g_hbuf[cur][1][0][0], xs);
    out[(size_t)t * B_ * H_ + (size_t)lane * H_ + j] = tanhf(acc[0]);
}

// ---------------------------------------------------------------------------
extern "C" void kernel_launch(void* const* d_in, const int* in_sizes, int n_in,
                              void* d_out, int out_size) {
    const int*   tokens   = (const int*)d_in[0];
    const float* h0       = (const float*)d_in[1];
    const float* c0       = (const float*)d_in[2];
    const float* contexts = (const float*)d_in[3];
    const float* emb      = (const float*)d_in[4];
    const float* W_ih     = (const float*)d_in[5];
    const float* W_hh     = (const float*)d_in[6];
    const float* b_ih     = (const float*)d_in[7];
    const float* b_hh     = (const float*)d_in[8];
    const float* W_in     = (const float*)d_in[9];
    const float* b_in     = (const float*)d_in[10];
    const float* W_out    = (const float*)d_in[11];
    const float* b_out    = (const float*)d_in[12];
    float* out = (float*)d_out;

    const size_t stateBytes = (size_t)L_ * B_ * H_ * sizeof(float);

    // init state: h -> hbuf[1] (prev of t=0), c -> g_c
    cudaMemcpyToSymbolAsync(g_hbuf, h0, stateBytes, stateBytes,
                            cudaMemcpyDeviceToDevice, 0);
    cudaMemcpyToSymbolAsync(g_c, c0, stateBytes, 0, cudaMemcpyDeviceToDevice, 0);

    // hoisted layer-0 input projection for all timesteps
    k_pre0<<<dim3(G_ / 64, T_), 256>>>(tokens, emb, W_ih, b_ih, b_hh);

    const float* Wih1 = W_ih + (size_t)G_ * H_;
    const float* Whh1 = W_hh + (size_t)G_ * H_;
    const float* bih1 = b_ih + G_;
    const float* bhh1 = b_hh + G_;

    for (int t = 0; t < T_; t++) {
        int cur = t & 1;
        k_cell0<<<128, 256>>>(W_hh, t, cur);
        k_cell1<<<128, 256>>>(Wih1, Whh1, bih1, bhh1, cur);
        k_gamma<<<128, 256>>>(W_in, b_in, cur);
        k_attn<<<B_, 256>>>(contexts);
        k_out<<<128, 256>>>(W_out, b_out, out, t, cur);
    }

    // hT (lives in hbuf[1] since (T-1)&1 == 1), then cT
    cudaMemcpyFromSymbolAsync(out + (size_t)T_ * B_ * H_, g_hbuf, stateBytes,
                              stateBytes, cudaMemcpyDeviceToDevice, 0);
    cudaMemcpyFromSymbolAsync(out + (size_t)T_ * B_ * H_ + (size_t)L_ * B_ * H_,
                              g_c, stateBytes, 0, cudaMemcpyDeviceToDevice, 0);
}

// round 4
// speedup vs baseline: 1.0091x; 1.0091x over previous
#include <cuda_runtime.h>
#include <math.h>

// Problem constants
constexpr int H_ = 1024;
constexpr int G_ = 4096;   // 4*H
constexpr int B_ = 32;
constexpr int T_ = 64;
constexpr int S_ = 64;
constexpr int L_ = 2;
constexpr int KT = 256;        // K tile
constexpr int XST = KT + 4;    // padded smem stride (words): 260 -> conflict-free LDS.128

// Scratch (device globals: sanctioned alternative to cudaMalloc)
__device__ float g_pre0[(size_t)T_ * G_ * B_];   // [t][j][b], j-major: 33.5 MB
__device__ float g_hbuf[2][L_][B_][H_];          // ping-pong h state
__device__ float g_c[L_][B_][H_];                // c state
__device__ float g_gamma[B_][H_];
__device__ float g_ctx[B_][H_];

__device__ __forceinline__ float sigf(float x) { return 1.f / (1.f + expf(-x)); }

// Warp computes NR output rows for all 32 batches (lane = b).
// W0 = pointer to (row0, col0) of this warp's rows; rows are rstride floats apart,
// columns contiguous. x = [B][H] activations. xs = smem tile (B*XST floats).
// blockDim must be 256.
template <int NR>
__device__ __forceinline__ void accum(float* acc, const float* __restrict__ W0,
                                      size_t rstride, const float* __restrict__ x,
                                      float* xs) {
    const int tid = threadIdx.x;
    const int lane = tid & 31;
    for (int k0 = 0; k0 < H_; k0 += KT) {
        __syncthreads();
        for (int i = tid; i < B_ * KT; i += 256) {
            int b = i >> 8;           // KT == 256
            int k = i & (KT - 1);
            xs[b * XST + k] = x[b * H_ + k0 + k];
        }
        __syncthreads();
        const float* xp = xs + lane * XST;
        const float* wp = W0 + k0;
#pragma unroll 4
        for (int k = 0; k < KT; k += 4) {
            float4 xv = *(const float4*)(xp + k);
#pragma unroll
            for (int r = 0; r < NR; r++) {
                float4 wv = *(const float4*)(wp + (size_t)r * rstride + k);
                acc[r] = fmaf(xv.x, wv.x, acc[r]);
                acc[r] = fmaf(xv.y, wv.y, acc[r]);
                acc[r] = fmaf(xv.z, wv.z, acc[r]);
                acc[r] = fmaf(xv.w, wv.w, acc[r]);
            }
        }
    }
}

// ---------------------------------------------------------------------------
// Precompute layer-0 input gates for ALL timesteps:
//   pre0[t][j][b] = b_ih0[j] + b_hh0[j] + dot(emb[tok[t][b]], W_ih0[j])
// grid (G/64, T), block 256: 8 warps x 8 rows
// ---------------------------------------------------------------------------
__global__ void __launch_bounds__(256) k_pre0(const int* __restrict__ tokens,
                                              const float* __restrict__ emb,
                                              const float* __restrict__ Wih0,
                                              const float* __restrict__ bih0,
                                              const float* __restrict__ bhh0) {
    __shared__ float xs[B_ * XST];
    __shared__ int tok_sh[B_];
    const int tid = threadIdx.x, wid = tid >> 5, lane = tid & 31;
    const int t = blockIdx.y;
    const int j0 = blockIdx.x * 64 + wid * 8;
    if (tid < B_) tok_sh[tid] = tokens[t * B_ + tid];

    float acc[8];
#pragma unroll
    for (int r = 0; r < 8; r++) acc[r] = bih0[j0 + r] + bhh0[j0 + r];

    for (int k0 = 0; k0 < H_; k0 += KT) {
        __syncthreads();
        for (int i = tid; i < B_ * KT; i += 256) {
            int b = i >> 8;
            int k = i & (KT - 1);
            xs[b * XST + k] = emb[(size_t)tok_sh[b] * H_ + k0 + k];
        }
        __syncthreads();
        const float* xp = xs + lane * XST;
        const float* wp = Wih0 + (size_t)j0 * H_ + k0;
#pragma unroll 2
        for (int k = 0; k < KT; k += 4) {
            float4 xv = *(const float4*)(xp + k);
#pragma unroll
            for (int r = 0; r < 8; r++) {
                float4 wv = *(const float4*)(wp + (size_t)r * H_ + k);
                acc[r] = fmaf(xv.x, wv.x, acc[r]);
                acc[r] = fmaf(xv.y, wv.y, acc[r]);
                acc[r] = fmaf(xv.z, wv.z, acc[r]);
                acc[r] = fmaf(xv.w, wv.w, acc[r]);
            }
        }
    }
    float* pre = g_pre0 + ((size_t)t * G_ + j0) * B_;
#pragma unroll
    for (int r = 0; r < 8; r++) pre[r * B_ + lane] = acc[r];   // [t][j0+r][b]
}

// ---------------------------------------------------------------------------
// Layer-0 LSTM cell: gates = pre0[t] + h0_prev @ Whh0^T, fused nonlinearity.
// grid 128, block 256: warp handles 1 jj (4 gate rows jj, jj+H, jj+2H, jj+3H).
// ---------------------------------------------------------------------------
__global__ void __launch_bounds__(256) k_cell0(const float* __restrict__ Whh0,
                                               int t, int cur) {
    __shared__ float xs[B_ * XST];
    const int tid = threadIdx.x, wid = tid >> 5, lane = tid & 31;
    const int jj = blockIdx.x * 8 + wid;

    float acc[4];
    const float* pre = g_pre0 + ((size_t)t * G_ + jj) * B_;
#pragma unroll
    for (int g = 0; g < 4; g++) acc[g] = pre[(size_t)g * H_ * B_ + lane];

    accum<4>(acc, Whh0 + (size_t)jj * H_, (size_t)H_ * H_,
             &g_hbuf[1 - cur][0][0][0], xs);

    float c1 = sigf(acc[1]) * g_c[0][lane][jj] + sigf(acc[0]) * tanhf(acc[2]);
    g_c[0][lane][jj] = c1;
    g_hbuf[cur][0][lane][jj] = sigf(acc[3]) * tanhf(c1);
}

// ---------------------------------------------------------------------------
// Layer-1 LSTM cell: gates = h0_cur @ Wih1^T + h1_prev @ Whh1^T + biases.
// ---------------------------------------------------------------------------
__global__ void __launch_bounds__(256) k_cell1(const float* __restrict__ Wih1,
                                               const float* __restrict__ Whh1,
                                               const float* __restrict__ bih1,
                                               const float* __restrict__ bhh1,
                                               int cur) {
    __shared__ float xs[B_ * XST];
    const int tid = threadIdx.x, wid = tid >> 5, lane = tid & 31;
    const int jj = blockIdx.x * 8 + wid;

    float acc[4];
#pragma unroll
    for (int g = 0; g < 4; g++) acc[g] = bih1[g * H_ + jj] + bhh1[g * H_ + jj];

    accum<4>(acc, Wih1 + (size_t)jj * H_, (size_t)H_ * H_,
             &g_hbuf[cur][0][0][0], xs);
    accum<4>(acc, Whh1 + (size_t)jj * H_, (size_t)H_ * H_,
             &g_hbuf[1 - cur][1][0][0], xs);

    float c1 = sigf(acc[1]) * g_c[1][lane][jj] + sigf(acc[0]) * tanhf(acc[2]);
    g_c[1][lane][jj] = c1;
    g_hbuf[cur][1][lane][jj] = sigf(acc[3]) * tanhf(c1);
}

// ---------------------------------------------------------------------------
// gamma = h1 @ W_in^T + b_in.  grid 128, 8 warps x 1 row.
// ---------------------------------------------------------------------------
__global__ void __launch_bounds__(256) k_gamma(const float* __restrict__ W_in,
                                               const float* __restrict__ b_in,
                                               int cur) {
    __shared__ float xs[B_ * XST];
    const int tid = threadIdx.x, wid = tid >> 5, lane = tid & 31;
    const int j = blockIdx.x * 8 + wid;
    float acc[1] = {b_in[j]};
    accum<1>(acc, W_in + (size_t)j * H_, 0, &g_hbuf[cur][1][0][0], xs);
    g_gamma[lane][j] = acc[0];
}

// ---------------------------------------------------------------------------
// Attention per batch element: scores, softmax, context. grid B, block 256.
// ---------------------------------------------------------------------------
__global__ void __launch_bounds__(256) k_attn(const float* __restrict__ contexts) {
    __shared__ float gs[H_];
    __shared__ float w_sh[S_];
    const int tid = threadIdx.x, wid = tid >> 5, lane = tid & 31;
    const int b = blockIdx.x;

    for (int i = tid; i < H_; i += 256) gs[i] = g_gamma[b][i];
    __syncthreads();

    // scores: 8 warps x 8 s each, lanes over k
#pragma unroll
    for (int si = 0; si < S_ / 8; si++) {
        int s = wid * (S_ / 8) + si;
        const float* cp = contexts + ((size_t)b * S_ + s) * H_;
        float a = 0.f;
        for (int k = lane; k < H_; k += 32) a = fmaf(cp[k], gs[k], a);
#pragma unroll
        for (int o = 16; o; o >>= 1) a += __shfl_xor_sync(0xffffffffu, a, o);
        if (lane == 0) w_sh[s] = a;
    }
    __syncthreads();

    // softmax over S=64 (warp 0, 2 values/lane)
    if (wid == 0) {
        float v0 = w_sh[lane], v1 = w_sh[lane + 32];
        float m = fmaxf(v0, v1);
#pragma unroll
        for (int o = 16; o; o >>= 1) m = fmaxf(m, __shfl_xor_sync(0xffffffffu, m, o));
        float e0 = expf(v0 - m), e1 = expf(v1 - m);
        float ssum = e0 + e1;
#pragma unroll
        for (int o = 16; o; o >>= 1) ssum += __shfl_xor_sync(0xffffffffu, ssum, o);
        float inv = 1.f / ssum;
        w_sh[lane] = e0 * inv;
        w_sh[lane + 32] = e1 * inv;
    }
    __syncthreads();

    // ctx[k] = sum_s w[s] * contexts[b][s][k]
#pragma unroll
    for (int i = 0; i < H_ / 256; i++) {
        int k = tid + i * 256;
        const float* cp = contexts + (size_t)b * S_ * H_ + k;
        float a = 0.f;
#pragma unroll 8
        for (int s = 0; s < S_; s++) a = fmaf(w_sh[s], cp[(size_t)s * H_], a);
        g_ctx[b][k] = a;
    }
}

// ---------------------------------------------------------------------------
// out[t][b][j] = tanh(b_out[j] + W_out[j,:H].ctx + W_out[j,H:].h1)
// ---------------------------------------------------------------------------
__global__ void __launch_bounds__(256) k_out(const float* __restrict__ W_out,
                                             const float* __restrict__ b_out,
                                             float* __restrict__ out, int t, int cur) {
    __shared__ float xs[B_ * XST];
    const int tid = threadIdx.x, wid = tid >> 5, lane = tid & 31;
    const int j = blockIdx.x * 8 + wid;
    float acc[1] = {b_out[j]};
    accum<1>(acc, W_out + (size_t)j * 2 * H_, 0, &g_ctx[0][0], xs);
    accum<1>(acc, W_out + (size_t)j * 2 * H_ + H_, 0, &g_hbuf[cur][1][0][0], xs);
    out[(size_t)t * B_ * H_ + (size_t)lane * H_ + j] = tanhf(acc[0]);
}

// ---------------------------------------------------------------------------
extern "C" void kernel_launch(void* const* d_in, const int* in_sizes, int n_in,
                              void* d_out, int out_size) {
    const int*   tokens   = (const int*)d_in[0];
    const float* h0       = (const float*)d_in[1];
    const float* c0       = (const float*)d_in[2];
    const float* contexts = (const float*)d_in[3];
    const float* emb      = (const float*)d_in[4];
    const float* W_ih     = (const float*)d_in[5];
    const float* W_hh     = (const float*)d_in[6];
    const float* b_ih     = (const float*)d_in[7];
    const float* b_hh     = (const float*)d_in[8];
    const float* W_in     = (const float*)d_in[9];
    const float* b_in     = (const float*)d_in[10];
    const float* W_out    = (const float*)d_in[11];
    const float* b_out    = (const float*)d_in[12];
    float* out = (float*)d_out;

    const size_t stateBytes = (size_t)L_ * B_ * H_ * sizeof(float);

    // init state: h -> hbuf[1] (prev of t=0), c -> g_c
    cudaMemcpyToSymbolAsync(g_hbuf, h0, stateBytes, stateBytes,
                            cudaMemcpyDeviceToDevice, 0);
    cudaMemcpyToSymbolAsync(g_c, c0, stateBytes, 0, cudaMemcpyDeviceToDevice, 0);

    // hoisted layer-0 input projection for all timesteps
    k_pre0<<<dim3(G_ / 64, T_), 256>>>(tokens, emb, W_ih, b_ih, b_hh);

    const float* Wih1 = W_ih + (size_t)G_ * H_;
    const float* Whh1 = W_hh + (size_t)G_ * H_;
    const float* bih1 = b_ih + G_;
    const float* bhh1 = b_hh + G_;

    for (int t = 0; t < T_; t++) {
        int cur = t & 1;
        k_cell0<<<128, 256>>>(W_hh, t, cur);
        k_cell1<<<128, 256>>>(Wih1, Whh1, bih1, bhh1, cur);
        k_gamma<<<128, 256>>>(W_in, b_in, cur);
        k_attn<<<B_, 256>>>(contexts);
        k_out<<<128, 256>>>(W_out, b_out, out, t, cur);
    }

    // hT (lives in hbuf[1] since (T-1)&1 == 1), then cT
    cudaMemcpyFromSymbolAsync(out + (size_t)T_ * B_ * H_, g_hbuf, stateBytes,
                              stateBytes, cudaMemcpyDeviceToDevice, 0);
    cudaMemcpyFromSymbolAsync(out + (size_t)T_ * B_ * H_ + (size_t)L_ * B_ * H_,
                              g_c, stateBytes, 0, cudaMemcpyDeviceToDevice, 0);
}

// round 5
// speedup vs baseline: 2.4712x; 2.4490x over previous
#include <cuda_runtime.h>
#include <math.h>

// Problem constants
constexpr int H_ = 1024;
constexpr int G_ = 4096;   // 4*H
constexpr int B_ = 32;
constexpr int T_ = 64;
constexpr int S_ = 64;
constexpr int L_ = 2;

// GEMM tiling
constexpr int KT  = 128;          // K tile
constexpr int XST = 132;          // padded smem row stride (words); quad-stride 33 == 1 mod 8 -> conflict-free LDS.128
constexpr int XB  = B_ * XST;     // x tile floats (4224)
constexpr int WB  = 16 * XST;     // w tile floats (2112)
constexpr int SMEM_BYTES = (2 * XB + 2 * WB) * 4;   // 50688 B

// Scratch (device globals: sanctioned alternative to cudaMalloc)
__device__ float g_pre0[(size_t)T_ * G_ * B_];   // [t][j][b]
__device__ float g_hbuf[2][L_][B_][H_];          // ping-pong h state
__device__ float g_c[L_][B_][H_];                // c state
__device__ float g_gamma[B_][H_];
__device__ float g_ctx[B_][H_];

__device__ __forceinline__ float sigf(float x) { return 1.f / (1.f + expf(-x)); }

__device__ __forceinline__ unsigned su32(const void* p) {
    return (unsigned)__cvta_generic_to_shared(p);
}
#define CPA16(d, s) asm volatile("cp.async.ca.shared.global [%0], [%1], 16;" :: "r"(d), "l"(s) : "memory")
#define CP_COMMIT() asm volatile("cp.async.commit_group;" ::: "memory")

__device__ __forceinline__ float unpack_sum(unsigned long long u) {
    float lo, hi;
    asm("mov.b64 {%0,%1}, %2;" : "=f"(lo), "=f"(hi) : "l"(u));
    return lo + hi;
}

// ---------------------------------------------------------------------------
// Staging helpers. Block = 128 threads. x tile: [B][KT] from [B][H_] activations
// (or gathered embedding rows). w tile: 16 rows x KT, row map:
//   global_row(rr) = rowBase + (rr&3)*sg + (rr>>2)*sc
// ---------------------------------------------------------------------------
__device__ __forceinline__ void stage_x(float* xsb, const float* __restrict__ X, int tid) {
#pragma unroll
    for (int i = tid; i < B_ * (KT / 4); i += 128) {
        int b = i >> 5, k4 = i & 31;
        CPA16(su32(xsb + b * XST + k4 * 4), X + (size_t)b * H_ + k4 * 4);
    }
}
__device__ __forceinline__ void stage_xg(float* xsb, const float* __restrict__ emb,
                                         const int* tok_sh, int k0, int tid) {
#pragma unroll
    for (int i = tid; i < B_ * (KT / 4); i += 128) {
        int b = i >> 5, k4 = i & 31;
        CPA16(su32(xsb + b * XST + k4 * 4),
              emb + (size_t)tok_sh[b] * H_ + k0 + k4 * 4);
    }
}
__device__ __forceinline__ void stage_w(float* wsb, const float* __restrict__ Wk0,
                                        size_t ldw, int rowBase, int sg, int sc, int tid) {
#pragma unroll
    for (int i = tid; i < 16 * (KT / 4); i += 128) {
        int rr = i >> 5, k4 = i & 31;
        int row = rowBase + (rr & 3) * sg + (rr >> 2) * sc;
        CPA16(su32(wsb + rr * XST + k4 * 4), Wk0 + (size_t)row * ldw + k4 * 4);
    }
}

// Inner compute: warp wid handles smem rows wid*4 .. wid*4+3, lane = batch.
// fma.rn.f32x2: even-k in lo, odd-k in hi of each 64-bit accumulator.
__device__ __forceinline__ void comp(const float* xsb, const float* wsb,
                                     unsigned long long acc[4], int wid, int lane) {
    const float* xp = xsb + lane * XST;
    const float* wp = wsb + wid * 4 * XST;
#pragma unroll 4
    for (int k = 0; k < KT; k += 4) {
        ulonglong2 xv = *(const ulonglong2*)(xp + k);
#pragma unroll
        for (int r = 0; r < 4; r++) {
            ulonglong2 wv = *(const ulonglong2*)(wp + r * XST + k);
            asm("fma.rn.f32x2 %0, %1, %2, %0;" : "+l"(acc[r]) : "l"(xv.x), "l"(wv.x));
            asm("fma.rn.f32x2 %0, %1, %2, %0;" : "+l"(acc[r]) : "l"(xv.y), "l"(wv.y));
        }
    }
}

// ---------------------------------------------------------------------------
// One K=H_ segment of GEMM, cp.async double-buffered.
// GATHER: x rows come from emb[tok[b]] instead of X[b].
// ---------------------------------------------------------------------------
template <bool GATHER>
__device__ __forceinline__ void gemm_seg(float* sm,
                                         const float* __restrict__ X,
                                         const int* tok_sh,
                                         const float* __restrict__ W, size_t ldw,
                                         int rowBase, int sg, int sc,
                                         unsigned long long acc[4],
                                         int tid, int wid, int lane) {
    float* xs = sm;
    float* ws = sm + 2 * XB;
    if (GATHER) stage_xg(xs, X, tok_sh, 0, tid);
    else        stage_x(xs, X, tid);
    stage_w(ws, W, ldw, rowBase, sg, sc, tid);
    CP_COMMIT();
    constexpr int NT = H_ / KT;   // 8
    for (int t = 0; t < NT; t++) {
        const int cb = t & 1;
        if (t + 1 < NT) {
            const int nb = cb ^ 1;
            if (GATHER) stage_xg(xs + nb * XB, X, tok_sh, (t + 1) * KT, tid);
            else        stage_x(xs + nb * XB, X + (t + 1) * KT, tid);
            stage_w(ws + nb * WB, W + (size_t)(t + 1) * KT, ldw, rowBase, sg, sc, tid);
            CP_COMMIT();
            asm volatile("cp.async.wait_group 1;" ::: "memory");
        } else {
            asm volatile("cp.async.wait_group 0;" ::: "memory");
        }
        __syncthreads();
        comp(xs + cb * XB, ws + cb * WB, acc, wid, lane);
        __syncthreads();
    }
}

// ---------------------------------------------------------------------------
// pre0[t][j][b] = b_ih0[j] + b_hh0[j] + dot(emb[tok[t][b]], W_ih0[j])
// grid (G/16, T), block 128
// ---------------------------------------------------------------------------
__global__ void __launch_bounds__(128) k_pre0(const int* __restrict__ tokens,
                                              const float* __restrict__ emb,
                                              const float* __restrict__ Wih0,
                                              const float* __restrict__ bih0,
                                              const float* __restrict__ bhh0) {
    extern __shared__ float sm[];
    __shared__ int tok_sh[B_];
    const int tid = threadIdx.x, wid = tid >> 5, lane = tid & 31;
    const int t = blockIdx.y;
    const int j0 = blockIdx.x * 16;
    if (tid < B_) tok_sh[tid] = tokens[t * B_ + tid];
    __syncthreads();

    unsigned long long acc[4] = {0ull, 0ull, 0ull, 0ull};
    gemm_seg<true>(sm, emb, tok_sh, Wih0, H_, j0, 1, 4, acc, tid, wid, lane);

#pragma unroll
    for (int r = 0; r < 4; r++) {
        int j = j0 + wid * 4 + r;
        g_pre0[((size_t)t * G_ + j) * B_ + lane] =
            unpack_sum(acc[r]) + bih0[j] + bhh0[j];
    }
}

// ---------------------------------------------------------------------------
// Layer-0 cell: gates = pre0[t] + h0_prev @ Whh0^T. grid 256, block 128.
// Warp handles one h-col j; acc[g] = gate rows {j, H+j, 2H+j, 3H+j}.
// ---------------------------------------------------------------------------
__global__ void __launch_bounds__(128) k_cell0(const float* __restrict__ Whh0,
                                               int t, int cur) {
    extern __shared__ float sm[];
    const int tid = threadIdx.x, wid = tid >> 5, lane = tid & 31;
    const int j0 = blockIdx.x * 4;

    unsigned long long acc[4] = {0ull, 0ull, 0ull, 0ull};
    gemm_seg<false>(sm, &g_hbuf[1 - cur][0][0][0], nullptr,
                    Whh0, H_, j0, H_, 1, acc, tid, wid, lane);

    const int j = j0 + wid;
    const float* pre = g_pre0 + (size_t)t * G_ * B_;
    float a_i = unpack_sum(acc[0]) + pre[(size_t)(0 * H_ + j) * B_ + lane];
    float a_f = unpack_sum(acc[1]) + pre[(size_t)(1 * H_ + j) * B_ + lane];
    float a_g = unpack_sum(acc[2]) + pre[(size_t)(2 * H_ + j) * B_ + lane];
    float a_o = unpack_sum(acc[3]) + pre[(size_t)(3 * H_ + j) * B_ + lane];
    float c1 = sigf(a_f) * g_c[0][lane][j] + sigf(a_i) * tanhf(a_g);
    g_c[0][lane][j] = c1;
    g_hbuf[cur][0][lane][j] = sigf(a_o) * tanhf(c1);
}

// ---------------------------------------------------------------------------
// Layer-1 cell: gates = h0_cur @ Wih1^T + h1_prev @ Whh1^T + biases.
// ---------------------------------------------------------------------------
__global__ void __launch_bounds__(128) k_cell1(const float* __restrict__ Wih1,
                                               const float* __restrict__ Whh1,
                                               const float* __restrict__ bih1,
                                               const float* __restrict__ bhh1,
                                               int cur) {
    extern __shared__ float sm[];
    const int tid = threadIdx.x, wid = tid >> 5, lane = tid & 31;
    const int j0 = blockIdx.x * 4;

    unsigned long long acc[4] = {0ull, 0ull, 0ull, 0ull};
    gemm_seg<false>(sm, &g_hbuf[cur][0][0][0], nullptr,
                    Wih1, H_, j0, H_, 1, acc, tid, wid, lane);
    gemm_seg<false>(sm, &g_hbuf[1 - cur][1][0][0], nullptr,
                    Whh1, H_, j0, H_, 1, acc, tid, wid, lane);

    const int j = j0 + wid;
    float a_i = unpack_sum(acc[0]) + bih1[0 * H_ + j] + bhh1[0 * H_ + j];
    float a_f = unpack_sum(acc[1]) + bih1[1 * H_ + j] + bhh1[1 * H_ + j];
    float a_g = unpack_sum(acc[2]) + bih1[2 * H_ + j] + bhh1[2 * H_ + j];
    float a_o = unpack_sum(acc[3]) + bih1[3 * H_ + j] + bhh1[3 * H_ + j];
    float c1 = sigf(a_f) * g_c[1][lane][j] + sigf(a_i) * tanhf(a_g);
    g_c[1][lane][j] = c1;
    g_hbuf[cur][1][lane][j] = sigf(a_o) * tanhf(c1);
}

// ---------------------------------------------------------------------------
// gamma = h1 @ W_in^T + b_in. grid 64, block 128 (16 rows/block).
// ---------------------------------------------------------------------------
__global__ void __launch_bounds__(128) k_gamma(const float* __restrict__ W_in,
                                               const float* __restrict__ b_in,
                                               int cur) {
    extern __shared__ float sm[];
    const int tid = threadIdx.x, wid = tid >> 5, lane = tid & 31;
    const int j0 = blockIdx.x * 16;

    unsigned long long acc[4] = {0ull, 0ull, 0ull, 0ull};
    gemm_seg<false>(sm, &g_hbuf[cur][1][0][0], nullptr,
                    W_in, H_, j0, 1, 4, acc, tid, wid, lane);

#pragma unroll
    for (int r = 0; r < 4; r++) {
        int j = j0 + wid * 4 + r;
        g_gamma[lane][j] = unpack_sum(acc[r]) + b_in[j];
    }
}

// ---------------------------------------------------------------------------
// Attention per batch element. grid B, block 256. (unchanged, small)
// ---------------------------------------------------------------------------
__global__ void __launch_bounds__(256) k_attn(const float* __restrict__ contexts) {
    __shared__ float gs[H_];
    __shared__ float w_sh[S_];
    const int tid = threadIdx.x, wid = tid >> 5, lane = tid & 31;
    const int b = blockIdx.x;

    for (int i = tid; i < H_; i += 256) gs[i] = g_gamma[b][i];
    __syncthreads();

#pragma unroll
    for (int si = 0; si < S_ / 8; si++) {
        int s = wid * (S_ / 8) + si;
        const float* cp = contexts + ((size_t)b * S_ + s) * H_;
        float a = 0.f;
        for (int k = lane; k < H_; k += 32) a = fmaf(cp[k], gs[k], a);
#pragma unroll
        for (int o = 16; o; o >>= 1) a += __shfl_xor_sync(0xffffffffu, a, o);
        if (lane == 0) w_sh[s] = a;
    }
    __syncthreads();

    if (wid == 0) {
        float v0 = w_sh[lane], v1 = w_sh[lane + 32];
        float m = fmaxf(v0, v1);
#pragma unroll
        for (int o = 16; o; o >>= 1) m = fmaxf(m, __shfl_xor_sync(0xffffffffu, m, o));
        float e0 = expf(v0 - m), e1 = expf(v1 - m);
        float ssum = e0 + e1;
#pragma unroll
        for (int o = 16; o; o >>= 1) ssum += __shfl_xor_sync(0xffffffffu, ssum, o);
        float inv = 1.f / ssum;
        w_sh[lane] = e0 * inv;
        w_sh[lane + 32] = e1 * inv;
    }
    __syncthreads();

#pragma unroll
    for (int i = 0; i < H_ / 256; i++) {
        int k = tid + i * 256;
        const float* cp = contexts + (size_t)b * S_ * H_ + k;
        float a = 0.f;
#pragma unroll 8
        for (int s = 0; s < S_; s++) a = fmaf(w_sh[s], cp[(size_t)s * H_], a);
        g_ctx[b][k] = a;
    }
}

// ---------------------------------------------------------------------------
// out[t][b][j] = tanh(b_out[j] + W_out[j,:H].ctx + W_out[j,H:].h1)
// grid 64, block 128.
// ---------------------------------------------------------------------------
__global__ void __launch_bounds__(128) k_out(const float* __restrict__ W_out,
                                             const float* __restrict__ b_out,
                                             float* __restrict__ out, int t, int cur) {
    extern __shared__ float sm[];
    const int tid = threadIdx.x, wid = tid >> 5, lane = tid & 31;
    const int j0 = blockIdx.x * 16;

    unsigned long long acc[4] = {0ull, 0ull, 0ull, 0ull};
    gemm_seg<false>(sm, &g_ctx[0][0], nullptr,
                    W_out, 2 * H_, j0, 1, 4, acc, tid, wid, lane);
    gemm_seg<false>(sm, &g_hbuf[cur][1][0][0], nullptr,
                    W_out + H_, 2 * H_, j0, 1, 4, acc, tid, wid, lane);

#pragma unroll
    for (int r = 0; r < 4; r++) {
        int j = j0 + wid * 4 + r;
        out[(size_t)t * B_ * H_ + (size_t)lane * H_ + j] =
            tanhf(unpack_sum(acc[r]) + b_out[j]);
    }
}

// ---------------------------------------------------------------------------
extern "C" void kernel_launch(void* const* d_in, const int* in_sizes, int n_in,
                              void* d_out, int out_size) {
    const int*   tokens   = (const int*)d_in[0];
    const float* h0       = (const float*)d_in[1];
    const float* c0       = (const float*)d_in[2];
    const float* contexts = (const float*)d_in[3];
    const float* emb      = (const float*)d_in[4];
    const float* W_ih     = (const float*)d_in[5];
    const float* W_hh     = (const float*)d_in[6];
    const float* b_ih     = (const float*)d_in[7];
    const float* b_hh     = (const float*)d_in[8];
    const float* W_in     = (const float*)d_in[9];
    const float* b_in     = (const float*)d_in[10];
    const float* W_out    = (const float*)d_in[11];
    const float* b_out    = (const float*)d_in[12];
    float* out = (float*)d_out;

    cudaFuncSetAttribute(k_pre0,  cudaFuncAttributeMaxDynamicSharedMemorySize, SMEM_BYTES);
    cudaFuncSetAttribute(k_cell0, cudaFuncAttributeMaxDynamicSharedMemorySize, SMEM_BYTES);
    cudaFuncSetAttribute(k_cell1, cudaFuncAttributeMaxDynamicSharedMemorySize, SMEM_BYTES);
    cudaFuncSetAttribute(k_gamma, cudaFuncAttributeMaxDynamicSharedMemorySize, SMEM_BYTES);
    cudaFuncSetAttribute(k_out,   cudaFuncAttributeMaxDynamicSharedMemorySize, SMEM_BYTES);

    const size_t stateBytes = (size_t)L_ * B_ * H_ * sizeof(float);

    // init state: h -> hbuf[1] (prev of t=0), c -> g_c
    cudaMemcpyToSymbolAsync(g_hbuf, h0, stateBytes, stateBytes,
                            cudaMemcpyDeviceToDevice, 0);
    cudaMemcpyToSymbolAsync(g_c, c0, stateBytes, 0, cudaMemcpyDeviceToDevice, 0);

    // hoisted layer-0 input projection for all timesteps
    k_pre0<<<dim3(G_ / 16, T_), 128, SMEM_BYTES>>>(tokens, emb, W_ih, b_ih, b_hh);

    const float* Wih1 = W_ih + (size_t)G_ * H_;
    const float* Whh1 = W_hh + (size_t)G_ * H_;
    const float* bih1 = b_ih + G_;
    const float* bhh1 = b_hh + G_;

    for (int t = 0; t < T_; t++) {
        int cur = t & 1;
        k_cell0<<<H_ / 4, 128, SMEM_BYTES>>>(W_hh, t, cur);
        k_cell1<<<H_ / 4, 128, SMEM_BYTES>>>(Wih1, Whh1, bih1, bhh1, cur);
        k_gamma<<<H_ / 16, 128, SMEM_BYTES>>>(W_in, b_in, cur);
        k_attn<<<B_, 256>>>(contexts);
        k_out<<<H_ / 16, 128, SMEM_BYTES>>>(W_out, b_out, out, t, cur);
    }

    // hT (lives in hbuf[1] since (T-1)&1 == 1), then cT
    cudaMemcpyFromSymbolAsync(out + (size_t)T_ * B_ * H_, g_hbuf, stateBytes,
                              stateBytes, cudaMemcpyDeviceToDevice, 0);
    cudaMemcpyFromSymbolAsync(out + (size_t)T_ * B_ * H_ + (size_t)L_ * B_ * H_,
                              g_c, stateBytes, 0, cudaMemcpyDeviceToDevice, 0);
}

// round 6
// speedup vs baseline: 2.7014x; 1.0931x over previous
#include <cuda_runtime.h>
#include <math.h>

// Problem constants
constexpr int H_ = 1024;
constexpr int G_ = 4096;   // 4*H
constexpr int B_ = 32;
constexpr int T_ = 64;
constexpr int S_ = 64;
constexpr int L_ = 2;

// GEMM tiling
constexpr int KT  = 128;            // K tile
constexpr int XST = 132;            // padded smem row stride (words)
constexpr int XB  = B_ * XST;       // x tile floats (4224)
constexpr int WBMAX = 32 * XST;     // w tile floats, 32 rows max (4224)
constexpr int SMEM_STEPS = (2 * XB + 2 * WBMAX) * 4;   // 67584 B (persistent kernel)

constexpr int WB128 = 16 * XST;     // pre0 (128-thread) w tile
constexpr int SMEM_PRE0 = (2 * XB + 2 * WB128) * 4;    // 50688 B

constexpr int NBLK = 128;           // persistent grid (<=148 SMs, all co-resident)

// Scratch (device globals)
__device__ float g_pre0[(size_t)T_ * G_ * B_];   // [t][j][b]
__device__ float g_hbuf[2][L_][B_][H_];          // ping-pong h state
__device__ float g_c[L_][B_][H_];                // c state
__device__ float g_gamma[B_][H_];
__device__ float g_ctx[B_][H_];

// grid barrier state
__device__ unsigned g_bar_cnt;
__device__ volatile unsigned g_bar_gen;

__device__ __forceinline__ float sigf(float x) { return 1.f / (1.f + expf(-x)); }

__device__ __forceinline__ unsigned su32(const void* p) {
    return (unsigned)__cvta_generic_to_shared(p);
}
#define CPA16(d, s) asm volatile("cp.async.ca.shared.global [%0], [%1], 16;" :: "r"(d), "l"(s) : "memory")
#define CP_COMMIT() asm volatile("cp.async.commit_group;" ::: "memory")

__device__ __forceinline__ float unpack_sum(unsigned long long u) {
    float lo, hi;
    asm("mov.b64 {%0,%1}, %2;" : "=f"(lo), "=f"(hi) : "l"(u));
    return lo + hi;
}

// Grid-wide barrier (canonical fence + atomicInc + spin; all NBLK CTAs resident)
__device__ __forceinline__ void grid_bar() {
    __syncthreads();
    if (threadIdx.x == 0) {
        __threadfence();
        unsigned gen = g_bar_gen;
        if (atomicInc(&g_bar_cnt, NBLK - 1) == NBLK - 1) {
            g_bar_gen = gen + 1;           // release new generation
        } else {
            while (g_bar_gen == gen) { __nanosleep(128); }
        }
        __threadfence();
    }
    __syncthreads();
}

// ===========================================================================
// 256-thread GEMM machinery (persistent step kernel)
// Row map for smem row rr in [0, 8*NR): row = rowBase + (rr%NR)*sg + (rr/NR)*sc
// Warp wid computes smem rows wid*NR .. wid*NR+NR-1, lane = batch.
// ===========================================================================
__device__ __forceinline__ void stage_x256(float* xsb, const float* __restrict__ X, int tid) {
#pragma unroll
    for (int i = tid; i < B_ * (KT / 4); i += 256) {
        int b = i >> 5, k4 = i & 31;
        CPA16(su32(xsb + b * XST + k4 * 4), X + (size_t)b * H_ + k4 * 4);
    }
}
template <int NR>
__device__ __forceinline__ void stage_w256(float* wsb, const float* __restrict__ Wk0,
                                           size_t ldw, int rowBase, int sg, int sc, int tid) {
#pragma unroll
    for (int i = tid; i < 8 * NR * (KT / 4); i += 256) {
        int rr = i >> 5, k4 = i & 31;
        int row = rowBase + (rr % NR) * sg + (rr / NR) * sc;
        CPA16(su32(wsb + rr * XST + k4 * 4), Wk0 + (size_t)row * ldw + k4 * 4);
    }
}
template <int NR>
__device__ __forceinline__ void comp256(const float* xsb, const float* wsb,
                                        unsigned long long* acc, int wid, int lane) {
    const float* xp = xsb + lane * XST;
    const float* wp = wsb + wid * NR * XST;
#pragma unroll 4
    for (int k = 0; k < KT; k += 4) {
        ulonglong2 xv = *(const ulonglong2*)(xp + k);
#pragma unroll
        for (int r = 0; r < NR; r++) {
            ulonglong2 wv = *(const ulonglong2*)(wp + r * XST + k);
            asm("fma.rn.f32x2 %0, %1, %2, %0;" : "+l"(acc[r]) : "l"(xv.x), "l"(wv.x));
            asm("fma.rn.f32x2 %0, %1, %2, %0;" : "+l"(acc[r]) : "l"(xv.y), "l"(wv.y));
        }
    }
}
template <int NR>
__device__ __forceinline__ void gemm_seg256(float* sm, const float* __restrict__ X,
                                            const float* __restrict__ W, size_t ldw,
                                            int rowBase, int sg, int sc,
                                            unsigned long long* acc,
                                            int tid, int wid, int lane) {
    float* xs = sm;
    float* ws = sm + 2 * XB;
    stage_x256(xs, X, tid);
    stage_w256<NR>(ws, W, ldw, rowBase, sg, sc, tid);
    CP_COMMIT();
    constexpr int NT = H_ / KT;   // 8
    for (int t = 0; t < NT; t++) {
        const int cb = t & 1;
        if (t + 1 < NT) {
            const int nb = cb ^ 1;
            stage_x256(xs + nb * XB, X + (t + 1) * KT, tid);
            stage_w256<NR>(ws + nb * WBMAX, W + (size_t)(t + 1) * KT, ldw, rowBase, sg, sc, tid);
            CP_COMMIT();
            asm volatile("cp.async.wait_group 1;" ::: "memory");
        } else {
            asm volatile("cp.async.wait_group 0;" ::: "memory");
        }
        __syncthreads();
        comp256<NR>(xs + cb * XB, ws + cb * WBMAX, acc, wid, lane);
        __syncthreads();
    }
}

// ===========================================================================
// Persistent kernel: whole T-loop. grid = NBLK x 256 threads.
// Per step: cell0 | BAR | cell1 | BAR | gamma | BAR | attn | BAR | out
// (no barrier after out: its inputs are protected by the next 3 barriers)
// ===========================================================================
__global__ void __launch_bounds__(256) k_steps(const float* __restrict__ Whh0,
                                               const float* __restrict__ Wih1,
                                               const float* __restrict__ Whh1,
                                               const float* __restrict__ bih1,
                                               const float* __restrict__ bhh1,
                                               const float* __restrict__ W_in,
                                               const float* __restrict__ b_in,
                                               const float* __restrict__ W_out,
                                               const float* __restrict__ b_out,
                                               const float* __restrict__ contexts,
                                               float* __restrict__ out) {
    extern __shared__ float sm[];
    __shared__ float gs[H_];
    __shared__ float w_sh[S_];
    const int tid = threadIdx.x, wid = tid >> 5, lane = tid & 31;
    const int blk = blockIdx.x;

    for (int t = 0; t < T_; t++) {
        const int cur = t & 1;

        // ---- cell0: j = blk*8 + wid, gates r=0..3 at rows j + r*H ----
        {
            unsigned long long acc[4] = {0ull, 0ull, 0ull, 0ull};
            gemm_seg256<4>(sm, &g_hbuf[1 - cur][0][0][0], Whh0, H_,
                           blk * 8, H_, 1, acc, tid, wid, lane);
            const int j = blk * 8 + wid;
            const float* pre = g_pre0 + (size_t)t * G_ * B_;
            float a_i = unpack_sum(acc[0]) + pre[(size_t)(0 * H_ + j) * B_ + lane];
            float a_f = unpack_sum(acc[1]) + pre[(size_t)(1 * H_ + j) * B_ + lane];
            float a_g = unpack_sum(acc[2]) + pre[(size_t)(2 * H_ + j) * B_ + lane];
            float a_o = unpack_sum(acc[3]) + pre[(size_t)(3 * H_ + j) * B_ + lane];
            float c1 = sigf(a_f) * g_c[0][lane][j] + sigf(a_i) * tanhf(a_g);
            g_c[0][lane][j] = c1;
            g_hbuf[cur][0][lane][j] = sigf(a_o) * tanhf(c1);
        }
        grid_bar();

        // ---- cell1: gates = h0_cur@Wih1^T + h1_prev@Whh1^T + biases ----
        {
            unsigned long long acc[4] = {0ull, 0ull, 0ull, 0ull};
            gemm_seg256<4>(sm, &g_hbuf[cur][0][0][0], Wih1, H_,
                           blk * 8, H_, 1, acc, tid, wid, lane);
            gemm_seg256<4>(sm, &g_hbuf[1 - cur][1][0][0], Whh1, H_,
                           blk * 8, H_, 1, acc, tid, wid, lane);
            const int j = blk * 8 + wid;
            float a_i = unpack_sum(acc[0]) + bih1[0 * H_ + j] + bhh1[0 * H_ + j];
            float a_f = unpack_sum(acc[1]) + bih1[1 * H_ + j] + bhh1[1 * H_ + j];
            float a_g = unpack_sum(acc[2]) + bih1[2 * H_ + j] + bhh1[2 * H_ + j];
            float a_o = unpack_sum(acc[3]) + bih1[3 * H_ + j] + bhh1[3 * H_ + j];
            float c1 = sigf(a_f) * g_c[1][lane][j] + sigf(a_i) * tanhf(a_g);
            g_c[1][lane][j] = c1;
            g_hbuf[cur][1][lane][j] = sigf(a_o) * tanhf(c1);
        }
        grid_bar();

        // ---- gamma = h1 @ W_in^T + b_in: row j = blk*8 + wid ----
        {
            unsigned long long acc[1] = {0ull};
            gemm_seg256<1>(sm, &g_hbuf[cur][1][0][0], W_in, H_,
                           blk * 8, 0, 1, acc, tid, wid, lane);
            const int j = blk * 8 + wid;
            g_gamma[lane][j] = unpack_sum(acc[0]) + b_in[j];
        }
        grid_bar();

        // ---- attention: blocks 0..31, b = blk ----
        if (blk < B_) {
            const int b = blk;
            for (int i = tid; i < H_; i += 256) gs[i] = g_gamma[b][i];
            __syncthreads();
#pragma unroll
            for (int si = 0; si < S_ / 8; si++) {
                int s = wid * (S_ / 8) + si;
                const float* cp = contexts + ((size_t)b * S_ + s) * H_;
                float a = 0.f;
                for (int k = lane; k < H_; k += 32) a = fmaf(cp[k], gs[k], a);
#pragma unroll
                for (int o = 16; o; o >>= 1) a += __shfl_xor_sync(0xffffffffu, a, o);
                if (lane == 0) w_sh[s] = a;
            }
            __syncthreads();
            if (wid == 0) {
                float v0 = w_sh[lane], v1 = w_sh[lane + 32];
                float m = fmaxf(v0, v1);
#pragma unroll
                for (int o = 16; o; o >>= 1) m = fmaxf(m, __shfl_xor_sync(0xffffffffu, m, o));
                float e0 = expf(v0 - m), e1 = expf(v1 - m);
                float ssum = e0 + e1;
#pragma unroll
                for (int o = 16; o; o >>= 1) ssum += __shfl_xor_sync(0xffffffffu, ssum, o);
                float inv = 1.f / ssum;
                w_sh[lane] = e0 * inv;
                w_sh[lane + 32] = e1 * inv;
            }
            __syncthreads();
#pragma unroll
            for (int i = 0; i < H_ / 256; i++) {
                int k = tid + i * 256;
                const float* cp = contexts + (size_t)b * S_ * H_ + k;
                float a = 0.f;
#pragma unroll 8
                for (int s = 0; s < S_; s++) a = fmaf(w_sh[s], cp[(size_t)s * H_], a);
                g_ctx[b][k] = a;
            }
        }
        grid_bar();

        // ---- out[t][b][j] = tanh(b_out + W_out[:,:H].ctx + W_out[:,H:].h1) ----
        {
            unsigned long long acc[1] = {0ull};
            gemm_seg256<1>(sm, &g_ctx[0][0], W_out, 2 * H_,
                           blk * 8, 0, 1, acc, tid, wid, lane);
            gemm_seg256<1>(sm, &g_hbuf[cur][1][0][0], W_out + H_, 2 * H_,
                           blk * 8, 0, 1, acc, tid, wid, lane);
            const int j = blk * 8 + wid;
            out[(size_t)t * B_ * H_ + (size_t)lane * H_ + j] =
                tanhf(unpack_sum(acc[0]) + b_out[j]);
        }
        // no grid_bar here (safe: next writers of g_ctx/h1 are >=3 barriers away)
    }
}

// ===========================================================================
// pre0 (hoisted layer-0 input projection), 128-thread blocks — as in R5
// ===========================================================================
__device__ __forceinline__ void stage_xg128(float* xsb, const float* __restrict__ emb,
                                            const int* tok_sh, int k0, int tid) {
#pragma unroll
    for (int i = tid; i < B_ * (KT / 4); i += 128) {
        int b = i >> 5, k4 = i & 31;
        CPA16(su32(xsb + b * XST + k4 * 4),
              emb + (size_t)tok_sh[b] * H_ + k0 + k4 * 4);
    }
}
__device__ __forceinline__ void stage_w128(float* wsb, const float* __restrict__ Wk0,
                                           int rowBase, int tid) {
#pragma unroll
    for (int i = tid; i < 16 * (KT / 4); i += 128) {
        int rr = i >> 5, k4 = i & 31;
        int row = rowBase + (rr & 3) + (rr >> 2) * 4;
        CPA16(su32(wsb + rr * XST + k4 * 4), Wk0 + (size_t)row * H_ + k4 * 4);
    }
}

__global__ void __launch_bounds__(128) k_pre0(const int* __restrict__ tokens,
                                              const float* __restrict__ emb,
                                              const float* __restrict__ Wih0,
                                              const float* __restrict__ bih0,
                                              const float* __restrict__ bhh0) {
    extern __shared__ float sm[];
    __shared__ int tok_sh[B_];
    const int tid = threadIdx.x, wid = tid >> 5, lane = tid & 31;
    const int t = blockIdx.y;
    const int j0 = blockIdx.x * 16;
    if (tid < B_) tok_sh[tid] = tokens[t * B_ + tid];
    __syncthreads();

    float* xs = sm;
    float* ws = sm + 2 * XB;
    unsigned long long acc[4] = {0ull, 0ull, 0ull, 0ull};

    stage_xg128(xs, emb, tok_sh, 0, tid);
    stage_w128(ws, Wih0, j0, tid);
    CP_COMMIT();
    constexpr int NT = H_ / KT;
    for (int tt = 0; tt < NT; tt++) {
        const int cb = tt & 1;
        if (tt + 1 < NT) {
            const int nb = cb ^ 1;
            stage_xg128(xs + nb * XB, emb, tok_sh, (tt + 1) * KT, tid);
            stage_w128(ws + nb * WB128, Wih0 + (size_t)(tt + 1) * KT, j0, tid);
            CP_COMMIT();
            asm volatile("cp.async.wait_group 1;" ::: "memory");
        } else {
            asm volatile("cp.async.wait_group 0;" ::: "memory");
        }
        __syncthreads();
        {
            const float* xp = xs + cb * XB + lane * XST;
            const float* wp = ws + cb * WB128 + wid * 4 * XST;
#pragma unroll 4
            for (int k = 0; k < KT; k += 4) {
                ulonglong2 xv = *(const ulonglong2*)(xp + k);
#pragma unroll
                for (int r = 0; r < 4; r++) {
                    ulonglong2 wv = *(const ulonglong2*)(wp + r * XST + k);
                    asm("fma.rn.f32x2 %0, %1, %2, %0;" : "+l"(acc[r]) : "l"(xv.x), "l"(wv.x));
                    asm("fma.rn.f32x2 %0, %1, %2, %0;" : "+l"(acc[r]) : "l"(xv.y), "l"(wv.y));
                }
            }
        }
        __syncthreads();
    }
#pragma unroll
    for (int r = 0; r < 4; r++) {
        int j = j0 + wid * 4 + r;   // rr = wid*4+r -> row = (rr&3) + (rr>>2)*4 = r + wid*4
        g_pre0[((size_t)t * G_ + j) * B_ + lane] =
            unpack_sum(acc[r]) + bih0[j] + bhh0[j];
    }
}

// ---------------------------------------------------------------------------
extern "C" void kernel_launch(void* const* d_in, const int* in_sizes, int n_in,
                              void* d_out, int out_size) {
    const int*   tokens   = (const int*)d_in[0];
    const float* h0       = (const float*)d_in[1];
    const float* c0       = (const float*)d_in[2];
    const float* contexts = (const float*)d_in[3];
    const float* emb      = (const float*)d_in[4];
    const float* W_ih     = (const float*)d_in[5];
    const float* W_hh     = (const float*)d_in[6];
    const float* b_ih     = (const float*)d_in[7];
    const float* b_hh     = (const float*)d_in[8];
    const float* W_in     = (const float*)d_in[9];
    const float* b_in     = (const float*)d_in[10];
    const float* W_out    = (const float*)d_in[11];
    const float* b_out    = (const float*)d_in[12];
    float* out = (float*)d_out;

    cudaFuncSetAttribute(k_pre0,  cudaFuncAttributeMaxDynamicSharedMemorySize, SMEM_PRE0);
    cudaFuncSetAttribute(k_steps, cudaFuncAttributeMaxDynamicSharedMemorySize, SMEM_STEPS);

    const size_t stateBytes = (size_t)L_ * B_ * H_ * sizeof(float);

    // init state: h -> hbuf[1] (prev of t=0), c -> g_c
    cudaMemcpyToSymbolAsync(g_hbuf, h0, stateBytes, stateBytes,
                            cudaMemcpyDeviceToDevice, 0);
    cudaMemcpyToSymbolAsync(g_c, c0, stateBytes, 0, cudaMemcpyDeviceToDevice, 0);

    // hoisted layer-0 input projection for all timesteps
    k_pre0<<<dim3(G_ / 16, T_), 128, SMEM_PRE0>>>(tokens, emb, W_ih, b_ih, b_hh);

    const float* Wih1 = W_ih + (size_t)G_ * H_;
    const float* Whh1 = W_hh + (size_t)G_ * H_;
    const float* bih1 = b_ih + G_;
    const float* bhh1 = b_hh + G_;

    // entire recurrence in ONE persistent kernel
    k_steps<<<NBLK, 256, SMEM_STEPS>>>(W_hh, Wih1, Whh1, bih1, bhh1,
                                       W_in, b_in, W_out, b_out, contexts, out);

    // hT (lives in hbuf[1] since (T-1)&1 == 1), then cT
    cudaMemcpyFromSymbolAsync(out + (size_t)T_ * B_ * H_, g_hbuf, stateBytes,
                              stateBytes, cudaMemcpyDeviceToDevice, 0);
    cudaMemcpyFromSymbolAsync(out + (size_t)T_ * B_ * H_ + (size_t)L_ * B_ * H_,
                              g_c, stateBytes, 0, cudaMemcpyDeviceToDevice, 0);
}